// round 10
// baseline (speedup 1.0000x reference)
#include <cuda_runtime.h>
#include <stdint.h>
#include <math.h>

// =============================== constants ===============================
namespace {
constexpr int Bz = 8, S = 2048, Dh = 128;
constexpr int CH = 16, CR = S / CH;       // 16 split-K chunks of 128 rows
constexpr int PITCHB = 272;               // smem row pitch bytes (136 bf16)
constexpr int TILE = 128 * PITCHB;        // 34816 B per 128x128 bf16 image
constexpr int SMEM_SZ = 4 * TILE;         // 139264 B
constexpr int NT = 512;                   // threads per GEMM CTA (16 warps)
}

// =============================== scratch =================================
__device__ float    g_Mp[Bz * CH * 128 * 128];  // split-K fp32 partials (8 MB)
__device__ uint32_t g_Mh[Bz][8192];             // M hi, bf16x2 row-major [d][v]
__device__ uint32_t g_Ml[Bz][8192];             // M lo

// =============================== helpers =================================
__device__ __forceinline__ uint32_t smem_u32(const void* p) {
    uint32_t a;
    asm("{ .reg .u64 t; cvta.to.shared.u64 t, %1; cvt.u32.u64 %0, t; }"
        : "=r"(a) : "l"(p));
    return a;
}
// pack: low half = lo operand, high half = hi operand
__device__ __forceinline__ uint32_t cvt2(float hi, float lo) {
    uint32_t r;
    asm("cvt.rn.bf16x2.f32 %0, %1, %2;" : "=r"(r) : "f"(hi), "f"(lo));
    return r;
}
__device__ __forceinline__ void ldsm4(uint32_t* r, uint32_t a) {
    asm volatile("ldmatrix.sync.aligned.m8n8.x4.shared.b16 {%0,%1,%2,%3}, [%4];"
        : "=r"(r[0]), "=r"(r[1]), "=r"(r[2]), "=r"(r[3]) : "r"(a));
}
__device__ __forceinline__ void ldsm4t(uint32_t* r, uint32_t a) {
    asm volatile("ldmatrix.sync.aligned.m8n8.x4.trans.shared.b16 {%0,%1,%2,%3}, [%4];"
        : "=r"(r[0]), "=r"(r[1]), "=r"(r[2]), "=r"(r[3]) : "r"(a));
}
__device__ __forceinline__ void mma_bf16(float* d, const uint32_t* a,
                                         const uint32_t* b) {
    asm volatile(
        "mma.sync.aligned.m16n8k16.row.col.f32.bf16.bf16.f32 "
        "{%0,%1,%2,%3}, {%4,%5,%6,%7}, {%8,%9}, {%0,%1,%2,%3};"
        : "+f"(d[0]), "+f"(d[1]), "+f"(d[2]), "+f"(d[3])
        : "r"(a[0]), "r"(a[1]), "r"(a[2]), "r"(a[3]), "r"(b[0]), "r"(b[1]));
}

// convert one float4 -> hi/lo bf16x2 pairs and store at (row, col4) in
// pitched images
__device__ __forceinline__ void cvt_store(float4 x, char* hi, char* lo,
                                          int row, int c4) {
    uint32_t h0 = cvt2(x.y, x.x), h1 = cvt2(x.w, x.z);
    float a0 = __uint_as_float(h0 << 16);
    float a1 = __uint_as_float(h0 & 0xFFFF0000u);
    float a2 = __uint_as_float(h1 << 16);
    float a3 = __uint_as_float(h1 & 0xFFFF0000u);
    uint32_t l0 = cvt2(x.y - a1, x.x - a0);
    uint32_t l1 = cvt2(x.w - a3, x.z - a2);
    *(uint2*)(hi + row * PITCHB + c4 * 2) = make_uint2(h0, h1);
    *(uint2*)(lo + row * PITCHB + c4 * 2) = make_uint2(l0, l1);
}

// one k16 MMA step (ks) on the resident images; warp tile 32x32.
// ATRANS: A stored [k][m] (use ldmatrix.trans); else A stored [m][k].
template <bool ATRANS>
__device__ __forceinline__ void mma_step(uint32_t aA, uint32_t bA, int ks,
                                         float acc[2][4][4]) {
    uint32_t ah[2][4], al[2][4];
    if (ATRANS) {
        const uint32_t kb = (uint32_t)(ks * 16 * PITCHB);
        ldsm4t(ah[0], aA + kb);
        ldsm4t(ah[1], aA + kb + 32);
        ldsm4t(al[0], aA + kb + TILE);
        ldsm4t(al[1], aA + kb + TILE + 32);
    } else {
        const uint32_t kb = (uint32_t)(ks * 32);
        ldsm4(ah[0], aA + kb);
        ldsm4(ah[1], aA + kb + 16 * PITCHB);
        ldsm4(al[0], aA + kb + TILE);
        ldsm4(al[1], aA + kb + TILE + 16 * PITCHB);
    }
    const uint32_t kbB = (uint32_t)(ks * 16 * PITCHB);
    uint32_t bh[8], bl[8];
    ldsm4t(&bh[0], bA + kbB);
    ldsm4t(&bh[4], bA + kbB + 32);
    ldsm4t(&bl[0], bA + kbB + TILE);
    ldsm4t(&bl[4], bA + kbB + TILE + 32);
#pragma unroll
    for (int mt = 0; mt < 2; ++mt)
#pragma unroll
        for (int j = 0; j < 4; ++j) {
            float* d = acc[mt][j];
            mma_bf16(d, ah[mt], &bh[2 * j]);
            mma_bf16(d, al[mt], &bh[2 * j]);
            mma_bf16(d, ah[mt], &bl[2 * j]);
        }
}

// fragment base addresses (warp tile 32x32, 16 warps)
template <bool ATRANS>
__device__ __forceinline__ void frag_bases(uint32_t sb, int lane, int wid,
                                           uint32_t& aA, uint32_t& bA) {
    const int m_base = (wid & 3) * 32, n_base = (wid >> 2) * 32;
    if (ATRANS) {
        aA = sb + (uint32_t)((((lane & 7) + ((lane >> 4) << 3)) * PITCHB) +
                             (m_base + ((lane >> 3) & 1) * 8) * 2);
    } else {
        aA = sb + (uint32_t)(((m_base + (lane & 7) + (((lane >> 3) & 1) << 3)) *
                              PITCHB) + ((lane >> 4) << 3) * 2);
    }
    bA = sb + 2 * TILE +
         (uint32_t)((((lane & 7) + (((lane >> 3) & 1) << 3)) * PITCHB) +
                    (n_base + ((lane >> 4) << 3)) * 2);
}

// ========== kernel 1: split-K partial of M = K^T V (pipelined) ==========
__global__ void __launch_bounds__(NT, 1)
ktv_kernel(const float* __restrict__ Kp, const float* __restrict__ Vp) {
    extern __shared__ char sm[];
    const int tid = threadIdx.x, lane = tid & 31, wid = tid >> 5;
    const int b = blockIdx.x >> 4, c = blockIdx.x & 15;

    const float4* Ks = (const float4*)(Kp + (size_t)(b * S + c * CR) * Dh);
    const float4* Vs = (const float4*)(Vp + (size_t)(b * S + c * CR) * Dh);
    const int lrow = tid >> 5, lc4 = (tid & 31) * 4;  // slab-local position

    // prologue: slab 0 (rows 0..15)
    {
        float4 kf = Ks[tid], vf = Vs[tid];
        cvt_store(kf, sm, sm + TILE, lrow, lc4);
        cvt_store(vf, sm + 2 * TILE, sm + 3 * TILE, lrow, lc4);
    }
    __syncthreads();

    uint32_t aA, bA;
    frag_bases<true>(smem_u32(sm), lane, wid, aA, bA);

    float acc[2][4][4];
#pragma unroll
    for (int i = 0; i < 2; ++i)
#pragma unroll
        for (int j = 0; j < 4; ++j)
#pragma unroll
            for (int k = 0; k < 4; ++k) acc[i][j][k] = 0.f;

#pragma unroll
    for (int s = 0; s < 8; ++s) {
        float4 kf, vf;
        if (s < 7) {                       // prefetch slab s+1
            kf = Ks[(s + 1) * 512 + tid];
            vf = Vs[(s + 1) * 512 + tid];
        }
        mma_step<true>(aA, bA, s, acc);    // compute on slab s
        if (s < 7) {                       // convert+store slab s+1
            const int row = (s + 1) * 16 + lrow;
            cvt_store(kf, sm, sm + TILE, row, lc4);
            cvt_store(vf, sm + 2 * TILE, sm + 3 * TILE, row, lc4);
        }
        __syncthreads();
    }

    const int m_base = (wid & 3) * 32, n_base = (wid >> 2) * 32;
    const int g = lane >> 2, t = lane & 3;
    float* outp = g_Mp + ((size_t)(b * CH + c)) * 16384;
#pragma unroll
    for (int mt = 0; mt < 2; ++mt)
#pragma unroll
        for (int nt = 0; nt < 4; ++nt) {
            const int row = m_base + mt * 16 + g, col = n_base + nt * 8 + 2 * t;
            *(float2*)&outp[row * 128 + col] =
                make_float2(acc[mt][nt][0], acc[mt][nt][1]);
            *(float2*)&outp[(row + 8) * 128 + col] =
                make_float2(acc[mt][nt][2], acc[mt][nt][3]);
        }
}

// ====== kernel 2: reduce 16 partials -> M, convert to bf16 hi/lo ======
__global__ void __launch_bounds__(256, 1) reduce_kernel() {
    const int b = blockIdx.x >> 4, seg = blockIdx.x & 15;
    const int tid = threadIdx.x;
    const int d = seg * 8 + (tid >> 5), v0 = (tid & 31) * 4;
    const float* base = g_Mp + (size_t)b * CH * 16384 + d * 128 + v0;
    float4 s = make_float4(0.f, 0.f, 0.f, 0.f);
#pragma unroll
    for (int c = 0; c < CH; ++c) {
        float4 p = *(const float4*)(base + (size_t)c * 16384);
        s.x += p.x; s.y += p.y; s.z += p.z; s.w += p.w;
    }
    uint32_t h0 = cvt2(s.y, s.x), h1 = cvt2(s.w, s.z);
    float a0 = __uint_as_float(h0 << 16), a1 = __uint_as_float(h0 & 0xFFFF0000u);
    float a2 = __uint_as_float(h1 << 16), a3 = __uint_as_float(h1 & 0xFFFF0000u);
    uint32_t l0 = cvt2(s.y - a1, s.x - a0), l1 = cvt2(s.w - a3, s.z - a2);
    const int w = d * 64 + v0 / 2;   // 64 words per 128-bf16 row
    *(uint2*)&g_Mh[b][w] = make_uint2(h0, h1);
    *(uint2*)&g_Ml[b][w] = make_uint2(l0, l1);
}

// ========= kernel 3: O tile = Q tile @ M (scaled), pipelined over d =========
__global__ void __launch_bounds__(NT, 1)
qm_kernel(const float* __restrict__ Qp, const float* __restrict__ sfp,
          float* __restrict__ Op) {
    extern __shared__ char sm[];
    const int tid = threadIdx.x, lane = tid & 31, wid = tid >> 5;
    const int b = blockIdx.x >> 4, qt = blockIdx.x & 15;

    const float4* Qs = (const float4*)(Qp + (size_t)(b * S + qt * 128) * Dh);
    const uint2* mh = (const uint2*)g_Mh[b];   // 32 uint2 per d-row
    const uint2* ml = (const uint2*)g_Ml[b];

    // per-slab loader positions
    const int qrow = tid >> 2, qc = tid & 3;   // Q: row, 4-col group in slab
    const int mr = tid >> 5, mw = tid & 31;    // M: slab-local row, uint2 idx
    char* dh = sm + 2 * TILE;
    char* dl = sm + 3 * TILE;

    // prologue: slab 0 (d cols/rows 0..15)
    {
        float4 qf = Qs[qrow * 32 + qc];
        cvt_store(qf, sm, sm + TILE, qrow, qc * 4);
        *(uint2*)(dh + mr * PITCHB + mw * 8) = mh[mr * 32 + mw];
        *(uint2*)(dl + mr * PITCHB + mw * 8) = ml[mr * 32 + mw];
    }
    __syncthreads();

    uint32_t aA, bA;
    frag_bases<false>(smem_u32(sm), lane, wid, aA, bA);

    float acc[2][4][4];
#pragma unroll
    for (int i = 0; i < 2; ++i)
#pragma unroll
        for (int j = 0; j < 4; ++j)
#pragma unroll
            for (int k = 0; k < 4; ++k) acc[i][j][k] = 0.f;

#pragma unroll
    for (int s = 0; s < 8; ++s) {
        float4 qf;
        uint2 mhv, mlv;
        if (s < 7) {                       // prefetch slab s+1
            qf  = Qs[qrow * 32 + (s + 1) * 4 + qc];
            mhv = mh[((s + 1) * 16 + mr) * 32 + mw];
            mlv = ml[((s + 1) * 16 + mr) * 32 + mw];
        }
        mma_step<false>(aA, bA, s, acc);   // compute on slab s
        if (s < 7) {
            cvt_store(qf, sm, sm + TILE, qrow, (s + 1) * 16 + qc * 4);
            const int row = (s + 1) * 16 + mr;
            *(uint2*)(dh + row * PITCHB + mw * 8) = mhv;
            *(uint2*)(dl + row * PITCHB + mw * 8) = mlv;
        }
        __syncthreads();
    }

    const float inv = 1.0f / (sqrtf(128.0f) * sfp[0]);
    const int m_base = (wid & 3) * 32, n_base = (wid >> 2) * 32;
    const int g = lane >> 2, t = lane & 3;
    float* outp = Op + (size_t)(b * S + qt * 128) * 128;
#pragma unroll
    for (int mt = 0; mt < 2; ++mt)
#pragma unroll
        for (int nt = 0; nt < 4; ++nt) {
            const int row = m_base + mt * 16 + g, col = n_base + nt * 8 + 2 * t;
            *(float2*)&outp[row * 128 + col] =
                make_float2(acc[mt][nt][0] * inv, acc[mt][nt][1] * inv);
            *(float2*)&outp[(row + 8) * 128 + col] =
                make_float2(acc[mt][nt][2] * inv, acc[mt][nt][3] * inv);
        }
}

// =============================== launch ===============================
extern "C" void kernel_launch(void* const* d_in, const int* in_sizes, int n_in,
                              void* d_out, int out_size) {
    // metadata order: qk (unused), qk_scaling_factor, query, key, value
    const float* sf = (const float*)d_in[1];
    const float* Q  = (const float*)d_in[2];
    const float* K  = (const float*)d_in[3];
    const float* V  = (const float*)d_in[4];
    float* O        = (float*)d_out;

    cudaFuncSetAttribute(ktv_kernel,
                         cudaFuncAttributeMaxDynamicSharedMemorySize, SMEM_SZ);
    cudaFuncSetAttribute(qm_kernel,
                         cudaFuncAttributeMaxDynamicSharedMemorySize, SMEM_SZ);

    ktv_kernel<<<Bz * CH, NT, SMEM_SZ>>>(K, V);
    reduce_kernel<<<Bz * CH, 256>>>();
    qm_kernel<<<Bz * CH, NT, SMEM_SZ>>>(Q, sf, O);
}

// round 13
// speedup vs baseline: 1.0015x; 1.0015x over previous
#include <cuda_runtime.h>
#include <stdint.h>
#include <math.h>

// =============================== constants ===============================
namespace {
constexpr int Bz = 8, S = 2048, Dh = 128;
constexpr int CH = 16, CR = S / CH;       // 16 split-K chunks of 128 rows
constexpr int PITCHB = 272;               // smem row pitch bytes (136 bf16)
constexpr int TILE = 128 * PITCHB;        // 34816 B per 128x128 bf16 image
constexpr int NT = 512;                   // threads per GEMM CTA (16 warps)
// ktv: 4-slot fp32 staging ring, 16 KB/slot (K slab 8KB + V slab 8KB)
constexpr int STG = 4 * TILE;             // staging base (after 4 images)
constexpr int SLOT_KTV = 16384;
constexpr int SMEM_KTV = STG + 4 * SLOT_KTV;   // 204800 B
// qm: 4-slot Q staging ring, 8 KB/slot
constexpr int SLOT_QM = 8192;
constexpr int SMEM_QM = STG + 4 * SLOT_QM;     // 172032 B
}

// =============================== scratch =================================
__device__ float    g_Mp[Bz * CH * 128 * 128];  // split-K fp32 partials (8 MB)
__device__ uint32_t g_Mh[Bz][8192];             // M hi, bf16x2 row-major [d][v]
__device__ uint32_t g_Ml[Bz][8192];             // M lo

// =============================== helpers =================================
__device__ __forceinline__ uint32_t smem_u32(const void* p) {
    uint32_t a;
    asm("{ .reg .u64 t; cvta.to.shared.u64 t, %1; cvt.u32.u64 %0, t; }"
        : "=r"(a) : "l"(p));
    return a;
}
__device__ __forceinline__ void cp16(uint32_t dst, const void* src) {
    asm volatile("cp.async.cg.shared.global [%0], [%1], 16;"
                 :: "r"(dst), "l"(src));
}
__device__ __forceinline__ void cp_commit() {
    asm volatile("cp.async.commit_group;");
}
template <int N>
__device__ __forceinline__ void cp_wait() {
    asm volatile("cp.async.wait_group %0;" :: "n"(N));
}
// pack: low half = lo operand, high half = hi operand
__device__ __forceinline__ uint32_t cvt2(float hi, float lo) {
    uint32_t r;
    asm("cvt.rn.bf16x2.f32 %0, %1, %2;" : "=r"(r) : "f"(hi), "f"(lo));
    return r;
}
__device__ __forceinline__ void ldsm4(uint32_t* r, uint32_t a) {
    asm volatile("ldmatrix.sync.aligned.m8n8.x4.shared.b16 {%0,%1,%2,%3}, [%4];"
        : "=r"(r[0]), "=r"(r[1]), "=r"(r[2]), "=r"(r[3]) : "r"(a));
}
__device__ __forceinline__ void ldsm4t(uint32_t* r, uint32_t a) {
    asm volatile("ldmatrix.sync.aligned.m8n8.x4.trans.shared.b16 {%0,%1,%2,%3}, [%4];"
        : "=r"(r[0]), "=r"(r[1]), "=r"(r[2]), "=r"(r[3]) : "r"(a));
}
__device__ __forceinline__ void mma_bf16(float* d, const uint32_t* a,
                                         const uint32_t* b) {
    asm volatile(
        "mma.sync.aligned.m16n8k16.row.col.f32.bf16.bf16.f32 "
        "{%0,%1,%2,%3}, {%4,%5,%6,%7}, {%8,%9}, {%0,%1,%2,%3};"
        : "+f"(d[0]), "+f"(d[1]), "+f"(d[2]), "+f"(d[3])
        : "r"(a[0]), "r"(a[1]), "r"(a[2]), "r"(a[3]), "r"(b[0]), "r"(b[1]));
}

// convert one float4 -> hi/lo bf16x2 pairs, store at (row, col4) in images
__device__ __forceinline__ void cvt_store(float4 x, char* hi, char* lo,
                                          int row, int c4) {
    uint32_t h0 = cvt2(x.y, x.x), h1 = cvt2(x.w, x.z);
    float a0 = __uint_as_float(h0 << 16);
    float a1 = __uint_as_float(h0 & 0xFFFF0000u);
    float a2 = __uint_as_float(h1 << 16);
    float a3 = __uint_as_float(h1 & 0xFFFF0000u);
    uint32_t l0 = cvt2(x.y - a1, x.x - a0);
    uint32_t l1 = cvt2(x.w - a3, x.z - a2);
    *(uint2*)(hi + row * PITCHB + c4 * 2) = make_uint2(h0, h1);
    *(uint2*)(lo + row * PITCHB + c4 * 2) = make_uint2(l0, l1);
}

// one k16 MMA step (ks) on the resident images; warp tile 32x32.
// ATRANS: A stored [k][m] (ldmatrix.trans); else A stored [m][k].
template <bool ATRANS>
__device__ __forceinline__ void mma_step(uint32_t aA, uint32_t bA, int ks,
                                         float acc[2][4][4]) {
    uint32_t ah[2][4], al[2][4];
    if (ATRANS) {
        const uint32_t kb = (uint32_t)(ks * 16 * PITCHB);
        ldsm4t(ah[0], aA + kb);
        ldsm4t(ah[1], aA + kb + 32);
        ldsm4t(al[0], aA + kb + TILE);
        ldsm4t(al[1], aA + kb + TILE + 32);
    } else {
        const uint32_t kb = (uint32_t)(ks * 32);
        ldsm4(ah[0], aA + kb);
        ldsm4(ah[1], aA + kb + 16 * PITCHB);
        ldsm4(al[0], aA + kb + TILE);
        ldsm4(al[1], aA + kb + TILE + 16 * PITCHB);
    }
    const uint32_t kbB = (uint32_t)(ks * 16 * PITCHB);
    uint32_t bh[8], bl[8];
    ldsm4t(&bh[0], bA + kbB);
    ldsm4t(&bh[4], bA + kbB + 32);
    ldsm4t(&bl[0], bA + kbB + TILE);
    ldsm4t(&bl[4], bA + kbB + TILE + 32);
#pragma unroll
    for (int mt = 0; mt < 2; ++mt)
#pragma unroll
        for (int j = 0; j < 4; ++j) {
            float* d = acc[mt][j];
            mma_bf16(d, ah[mt], &bh[2 * j]);
            mma_bf16(d, al[mt], &bh[2 * j]);
            mma_bf16(d, ah[mt], &bl[2 * j]);
        }
}

// fragment base addresses (warp tile 32x32, 16 warps)
template <bool ATRANS>
__device__ __forceinline__ void frag_bases(uint32_t sb, int lane, int wid,
                                           uint32_t& aA, uint32_t& bA) {
    const int m_base = (wid & 3) * 32, n_base = (wid >> 2) * 32;
    if (ATRANS) {
        aA = sb + (uint32_t)((((lane & 7) + ((lane >> 4) << 3)) * PITCHB) +
                             (m_base + ((lane >> 3) & 1) * 8) * 2);
    } else {
        aA = sb + (uint32_t)(((m_base + (lane & 7) + (((lane >> 3) & 1) << 3)) *
                              PITCHB) + ((lane >> 4) << 3) * 2);
    }
    bA = sb + 2 * TILE +
         (uint32_t)((((lane & 7) + (((lane >> 3) & 1) << 3)) * PITCHB) +
                    (n_base + ((lane >> 4) << 3)) * 2);
}

// ===== kernel 1: split-K partial of M = K^T V (cp.async 4-deep ring) =====
__global__ void __launch_bounds__(NT, 1)
ktv_kernel(const float* __restrict__ Kp, const float* __restrict__ Vp) {
    extern __shared__ char sm[];
    const uint32_t sb = smem_u32(sm);
    const int tid = threadIdx.x, lane = tid & 31, wid = tid >> 5;
    const int b = blockIdx.x >> 4, c = blockIdx.x & 15;

    const char* Kb = (const char*)(Kp + (size_t)(b * S + c * CR) * Dh);
    const char* Vb = (const char*)(Vp + (size_t)(b * S + c * CR) * Dh);
    const int r = tid >> 5, ch = tid & 31;   // slab-local row, 16B chunk

    // issue cp.async for slab s into ring slot s&3 (K then V)
    auto issue = [&](int s) {
        const uint32_t slot = sb + STG + (s & 3) * SLOT_KTV;
        const int o = r * 512 + ch * 16;
        cp16(slot + o,        Kb + (size_t)(s * 16) * 512 + o);
        cp16(slot + 8192 + o, Vb + (size_t)(s * 16) * 512 + o);
    };
    // convert slab s from its ring slot into the bf16 images (thread-local
    // chunks: same (r, ch) this thread cp.async'd — no barrier needed)
    auto convert = [&](int s) {
        const char* slot = sm + STG + (s & 3) * SLOT_KTV;
        const int o = r * 512 + ch * 16;
        float4 kf = *(const float4*)(slot + o);
        float4 vf = *(const float4*)(slot + 8192 + o);
        const int row = s * 16 + r;
        cvt_store(kf, sm, sm + TILE, row, ch * 4);
        cvt_store(vf, sm + 2 * TILE, sm + 3 * TILE, row, ch * 4);
    };

    issue(0); cp_commit();
    issue(1); cp_commit();
    issue(2); cp_commit();
    issue(3); cp_commit();

    uint32_t aA, bA;
    frag_bases<true>(sb, lane, wid, aA, bA);
    float acc[2][4][4] = {};

    cp_wait<3>();          // slab 0 staged (own copies visible)
    convert(0);
    __syncthreads();       // publish slab-0 images

#pragma unroll
    for (int s = 0; s < 8; ++s) {
        if (s + 4 < 8) issue(s + 4);
        cp_commit();                       // always: keeps group count exact
        if (s < 7) {
            cp_wait<3>();                  // slab s+1 staged
            convert(s + 1);
        }
        mma_step<true>(aA, bA, s, acc);    // consume slab s images
        __syncthreads();                   // publish slab s+1 images
    }

    const int m_base = (wid & 3) * 32, n_base = (wid >> 2) * 32;
    const int g = lane >> 2, t = lane & 3;
    float* outp = g_Mp + ((size_t)(b * CH + c)) * 16384;
#pragma unroll
    for (int mt = 0; mt < 2; ++mt)
#pragma unroll
        for (int nt = 0; nt < 4; ++nt) {
            const int row = m_base + mt * 16 + g, col = n_base + nt * 8 + 2 * t;
            *(float2*)&outp[row * 128 + col] =
                make_float2(acc[mt][nt][0], acc[mt][nt][1]);
            *(float2*)&outp[(row + 8) * 128 + col] =
                make_float2(acc[mt][nt][2], acc[mt][nt][3]);
        }
}

// ====== kernel 2: reduce 16 partials -> M, convert to bf16 hi/lo ======
__global__ void __launch_bounds__(256, 1) reduce_kernel() {
    const int b = blockIdx.x >> 4, seg = blockIdx.x & 15;
    const int tid = threadIdx.x;
    const int d = seg * 8 + (tid >> 5), v0 = (tid & 31) * 4;
    const float* base = g_Mp + (size_t)b * CH * 16384 + d * 128 + v0;
    float4 s = make_float4(0.f, 0.f, 0.f, 0.f);
#pragma unroll
    for (int c = 0; c < CH; ++c) {
        float4 p = *(const float4*)(base + (size_t)c * 16384);
        s.x += p.x; s.y += p.y; s.z += p.z; s.w += p.w;
    }
    uint32_t h0 = cvt2(s.y, s.x), h1 = cvt2(s.w, s.z);
    float a0 = __uint_as_float(h0 << 16), a1 = __uint_as_float(h0 & 0xFFFF0000u);
    float a2 = __uint_as_float(h1 << 16), a3 = __uint_as_float(h1 & 0xFFFF0000u);
    uint32_t l0 = cvt2(s.y - a1, s.x - a0), l1 = cvt2(s.w - a3, s.z - a2);
    const int w = d * 64 + v0 / 2;   // 64 words per 128-bf16 row
    *(uint2*)&g_Mh[b][w] = make_uint2(h0, h1);
    *(uint2*)&g_Ml[b][w] = make_uint2(l0, l1);
}

// ===== kernel 3: O tile = Q tile @ M (scaled), cp.async pipelined =====
__global__ void __launch_bounds__(NT, 1)
qm_kernel(const float* __restrict__ Qp, const float* __restrict__ sfp,
          float* __restrict__ Op) {
    extern __shared__ char sm[];
    const uint32_t sb = smem_u32(sm);
    const int tid = threadIdx.x, lane = tid & 31, wid = tid >> 5;
    const int b = blockIdx.x >> 4, qt = blockIdx.x & 15;

    const char* Qb  = (const char*)(Qp + (size_t)(b * S + qt * 128) * Dh);
    const int qr = tid >> 2, qc = tid & 3;           // Q: row, 16B chunk
    // M loaders: tid<256 -> hi image, tid>=256 -> lo image
    const int hsel = tid >> 8, mr = (tid >> 4) & 15, mc = tid & 15;
    const char* msrc = hsel ? (const char*)g_Ml[b] : (const char*)g_Mh[b];
    const uint32_t mimg = sb + (hsel ? 3 : 2) * TILE;

    // slab s: Q columns 16s..16s+15 -> staging; M rows 16s..16s+15 -> images
    auto issue = [&](int s) {
        cp16(sb + STG + (s & 3) * SLOT_QM + qr * 64 + qc * 16,
             Qb + (size_t)qr * 512 + s * 64 + qc * 16);
        const int row = s * 16 + mr;
        cp16(mimg + row * PITCHB + mc * 16, msrc + (size_t)row * 256 + mc * 16);
    };
    auto convertQ = [&](int s) {
        float4 qf = *(const float4*)(sm + STG + (s & 3) * SLOT_QM +
                                     qr * 64 + qc * 16);
        cvt_store(qf, sm, sm + TILE, qr, s * 16 + qc * 4);
    };

    issue(0); cp_commit();
    issue(1); cp_commit();
    issue(2); cp_commit();
    issue(3); cp_commit();

    uint32_t aA, bA;
    frag_bases<false>(sb, lane, wid, aA, bA);
    float acc[2][4][4] = {};

    cp_wait<3>();          // slab 0 (Q staged + M image rows) complete
    convertQ(0);
    __syncthreads();       // publish slab-0 images

#pragma unroll
    for (int s = 0; s < 8; ++s) {
        if (s + 4 < 8) issue(s + 4);
        cp_commit();
        if (s < 7) {
            cp_wait<3>();
            convertQ(s + 1);
        }
        mma_step<false>(aA, bA, s, acc);
        __syncthreads();
    }

    const float inv = 1.0f / (sqrtf(128.0f) * sfp[0]);
    const int m_base = (wid & 3) * 32, n_base = (wid >> 2) * 32;
    const int g = lane >> 2, t = lane & 3;
    float* outp = Op + (size_t)(b * S + qt * 128) * 128;
#pragma unroll
    for (int mt = 0; mt < 2; ++mt)
#pragma unroll
        for (int nt = 0; nt < 4; ++nt) {
            const int row = m_base + mt * 16 + g, col = n_base + nt * 8 + 2 * t;
            *(float2*)&outp[row * 128 + col] =
                make_float2(acc[mt][nt][0] * inv, acc[mt][nt][1] * inv);
            *(float2*)&outp[(row + 8) * 128 + col] =
                make_float2(acc[mt][nt][2] * inv, acc[mt][nt][3] * inv);
        }
}

// =============================== launch ===============================
extern "C" void kernel_launch(void* const* d_in, const int* in_sizes, int n_in,
                              void* d_out, int out_size) {
    // metadata order: qk (unused), qk_scaling_factor, query, key, value
    const float* sf = (const float*)d_in[1];
    const float* Q  = (const float*)d_in[2];
    const float* K  = (const float*)d_in[3];
    const float* V  = (const float*)d_in[4];
    float* O        = (float*)d_out;

    cudaFuncSetAttribute(ktv_kernel,
                         cudaFuncAttributeMaxDynamicSharedMemorySize, SMEM_KTV);
    cudaFuncSetAttribute(qm_kernel,
                         cudaFuncAttributeMaxDynamicSharedMemorySize, SMEM_QM);

    ktv_kernel<<<Bz * CH, NT, SMEM_KTV>>>(K, V);
    reduce_kernel<<<Bz * CH, 256>>>();
    qm_kernel<<<Bz * CH, NT, SMEM_QM>>>(Q, sf, O);
}